// round 1
// baseline (speedup 1.0000x reference)
#include <cuda_runtime.h>
#include <math.h>

#define RR 4
#define NN 4096
#define EE 2048
#define FF 128
#define HDIM 256
#define EW (EE/32)   // 64 words per node row
#define NW (NN/32)   // 128 words per edge row

// ---------------- device scratch (allocation-free: static globals) ----------------
__device__ float    g_rw[RR];
__device__ float    g_sig[3][RR];
__device__ float    g_dv[RR*NN];                 // node scale per relation
__device__ float    g_cE[RR*EE];                 // rw^2 * de^2 per edge
__device__ unsigned g_maskN[(size_t)RR*NN*EW];   // bit e of node-row words
__device__ unsigned g_maskE[(size_t)RR*EE*NW];   // bit n of edge-row words
__device__ float    g_T [(size_t)RR*EE*HDIM];    // edge features
__device__ float    g_Hn[(size_t)RR*NN*HDIM];    // per-relation node features
__device__ float    g_pre[(size_t)NN*HDIM];      // pre-activation
__device__ float    g_h  [(size_t)NN*HDIM];      // post-activation hidden
__device__ float    g_mu[HDIM], g_var[HDIM];

// ---------------- prep: softmax(rel_attn), sigmoid(imp) ----------------
__global__ void prep_kernel(const float* __restrict__ rel, const float* __restrict__ imp) {
    if (threadIdx.x == 0) {
        float m = -1e30f;
        for (int r = 0; r < RR; r++) m = fmaxf(m, rel[r]);
        float e[RR], s = 0.f;
        for (int r = 0; r < RR; r++) { e[r] = expf(rel[r] - m); s += e[r]; }
        for (int r = 0; r < RR; r++) g_rw[r] = e[r] / s;
        for (int l = 0; l < 3; l++)
            for (int r = 0; r < RR; r++)
                g_sig[l][r] = 1.f / (1.f + expf(-imp[l*RR + r]));
    }
}

// ---------------- bitmask build: one warp per (r,n) row of H ----------------
__global__ void build_maskN_kernel(const float* __restrict__ H) {
    int gw   = blockIdx.x * (blockDim.x >> 5) + (threadIdx.x >> 5);
    int lane = threadIdx.x & 31;
    if (gw >= RR*NN) return;
    int r = gw / NN;
    const float* row = H + (size_t)gw * EE;
    unsigned w0 = 0, w1 = 0;
    int cnt = 0;
    #pragma unroll 8
    for (int k = 0; k < 64; k++) {
        float v = row[k*32 + lane];
        unsigned b = __ballot_sync(0xffffffffu, v != 0.0f);
        cnt += (v != 0.0f) ? 1 : 0;
        if (k == lane)      w0 = b;
        if (k == lane + 32) w1 = b;
    }
    g_maskN[(size_t)gw*EW + lane]      = w0;
    g_maskN[(size_t)gw*EW + 32 + lane] = w1;
    int tot = __reduce_add_sync(0xffffffffu, cnt);
    if (lane == 0)
        g_dv[gw] = 1.0f / sqrtf(g_rw[r] * (float)tot + 1e-8f);
}

// ---------------- 32x32 bit transpose: maskN -> maskE ----------------
__global__ void transpose_mask_kernel() {
    const int tilesPerR = (NN/32)*(EE/32);
    int gw   = blockIdx.x * (blockDim.x >> 5) + (threadIdx.x >> 5);
    int lane = threadIdx.x & 31;
    if (gw >= RR * tilesPerR) return;
    int r   = gw / tilesPerR;
    int rem = gw % tilesPerR;
    int nb  = rem / (EE/32);
    int eb  = rem % (EE/32);
    unsigned w = g_maskN[((size_t)r*NN + nb*32 + lane)*EW + eb];
    unsigned out = 0;
    #pragma unroll
    for (int j = 0; j < 32; j++) {
        unsigned b = __ballot_sync(0xffffffffu, (w >> j) & 1u);
        if (lane == j) out = b;
    }
    g_maskE[((size_t)r*EE + eb*32 + lane)*NW + nb] = out;
}

// ---------------- edge constants: cE = rw^2 / (rw*deg_e + eps) ----------------
__global__ void build_cE_kernel() {
    int gw   = blockIdx.x * (blockDim.x >> 5) + (threadIdx.x >> 5);
    int lane = threadIdx.x & 31;
    if (gw >= RR*EE) return;
    int r = gw / EE;
    const unsigned* row = g_maskE + (size_t)gw * NW;
    int cnt = 0;
    for (int k = lane; k < NW; k += 32) cnt += __popc(row[k]);
    cnt = __reduce_add_sync(0xffffffffu, cnt);
    if (lane == 0) {
        float rw = g_rw[r];
        g_cE[gw] = rw * rw / (rw * (float)cnt + 1e-8f);
    }
}

// ---------------- generic masked gather-SpMM ----------------
// out[r][t][colOff+c] = outScale[r][t] * sum_{s: mask bit set} srcScale?[r][s] * src[s][colOff+c]
// Block: 64 targets x 128 cols, 256 threads (8 warps x 8 targets), source staged in smem chunks of 64.
__global__ void gather_kernel(const unsigned* __restrict__ mask, int Tn, int Sn,
                              const float* __restrict__ src, long long srcRelStride, int srcRowStride,
                              const float* __restrict__ srcScale,
                              const float* __restrict__ outScale,
                              float* __restrict__ out, int outRowStride)
{
    __shared__ float4 s_src4[64][32];   // 64 rows x 128 floats = 32KB
    float* s_src = (float*)s_src4;

    const int Sw = Sn >> 5;
    const int tilesPerR = Tn >> 6;
    const int r   = blockIdx.x / tilesPerR;
    const int t0  = (blockIdx.x % tilesPerR) << 6;
    const int colOff = blockIdx.y << 7;
    const int tid = threadIdx.x, lane = tid & 31, w = tid >> 5;

    const float* srcBase = src + (size_t)r * srcRelStride + colOff;
    const float* sScale  = srcScale ? (srcScale + (size_t)r * Sn) : nullptr;

    float4 acc[8];
    #pragma unroll
    for (int j = 0; j < 8; j++) acc[j] = make_float4(0.f,0.f,0.f,0.f);

    const int chunks = Sn >> 6;
    for (int c = 0; c < chunks; c++) {
        const int baseS = c << 6;
        // stage scaled source chunk
        #pragma unroll
        for (int i = tid; i < 64*128; i += 256) {
            int row = i >> 7, col = i & 127;
            float v = srcBase[(size_t)(baseS + row) * srcRowStride + col];
            if (sScale) v *= sScale[baseS + row];
            s_src[row*128 + col] = v;
        }
        __syncthreads();

        #pragma unroll
        for (int j = 0; j < 8; j++) {
            int t = t0 + w*8 + j;
            const unsigned* mp = mask + ((size_t)r*Tn + t)*Sw + c*2;
            unsigned b0 = mp[0];
            unsigned b1 = mp[1];
            while (b0) {
                int bi = __ffs(b0) - 1; b0 &= b0 - 1;
                float4 v = s_src4[bi][lane];
                acc[j].x += v.x; acc[j].y += v.y; acc[j].z += v.z; acc[j].w += v.w;
            }
            while (b1) {
                int bi = __ffs(b1) - 1; b1 &= b1 - 1;
                float4 v = s_src4[32 + bi][lane];
                acc[j].x += v.x; acc[j].y += v.y; acc[j].z += v.z; acc[j].w += v.w;
            }
        }
        __syncthreads();
    }

    #pragma unroll
    for (int j = 0; j < 8; j++) {
        int t = t0 + w*8 + j;
        float sc = outScale[(size_t)r*Tn + t];
        float4 v = acc[j];
        v.x *= sc; v.y *= sc; v.z *= sc; v.w *= sc;
        reinterpret_cast<float4*>(out + ((size_t)r*Tn + t)*outRowStride + colOff)[lane] = v;
    }
}

// ---------------- relation-summed projection GEMM + epilogue ----------------
// out[n][o] = sum_r sig[r] * sum_f Hn[r][n][f] * W[r][f][o]  (+ bias, + optional residual)
__global__ void gemm_kernel(const float* __restrict__ A, int Fin, int Fout,
                            const float* __restrict__ W,
                            const float* __restrict__ sig,
                            const float* __restrict__ bias,
                            const float* __restrict__ resid,
                            float* __restrict__ out)
{
    __shared__ float sA[16][68];
    __shared__ float sB[16][68];
    const int n0 = blockIdx.x << 6, o0 = blockIdx.y << 6;
    const int tid = threadIdx.x;
    const int tx = tid & 15, ty = tid >> 4;

    float acc[4][4];
    #pragma unroll
    for (int i = 0; i < 4; i++)
        #pragma unroll
        for (int j = 0; j < 4; j++) acc[i][j] = 0.f;

    for (int r = 0; r < RR; r++) {
        const float sr = sig[r];
        const float* Ar = A + (size_t)r * NN * HDIM;
        const float* Wr = W + (size_t)r * Fin * Fout;
        for (int f0 = 0; f0 < Fin; f0 += 16) {
            // load A tile: sA[k][m] = A[n0+m][f0+k]
            {
                int k = tid & 15, mg = tid >> 4;
                #pragma unroll
                for (int mm = 0; mm < 4; mm++) {
                    int m = mg*4 + mm;
                    sA[k][m] = Ar[(size_t)(n0+m)*HDIM + f0 + k];
                }
            }
            // load B tile (scaled): sB[k][j] = sr * W[f0+k][o0+j]
            {
                int j = tid & 63, k0 = tid >> 6;
                #pragma unroll
                for (int kk = 0; kk < 4; kk++) {
                    int k = k0 + kk*4;
                    sB[k][j] = sr * Wr[(size_t)(f0+k)*Fout + o0 + j];
                }
            }
            __syncthreads();
            #pragma unroll
            for (int k = 0; k < 16; k++) {
                float4 a = *reinterpret_cast<const float4*>(&sA[k][ty*4]);
                float4 b = *reinterpret_cast<const float4*>(&sB[k][tx*4]);
                float av[4] = {a.x, a.y, a.z, a.w};
                float bv[4] = {b.x, b.y, b.z, b.w};
                #pragma unroll
                for (int i = 0; i < 4; i++)
                    #pragma unroll
                    for (int j = 0; j < 4; j++)
                        acc[i][j] += av[i] * bv[j];
            }
            __syncthreads();
        }
    }

    #pragma unroll
    for (int i = 0; i < 4; i++) {
        int n = n0 + ty*4 + i;
        #pragma unroll
        for (int j = 0; j < 4; j++) {
            int o = o0 + tx*4 + j;
            float v = acc[i][j] + bias[o];
            if (resid) v += resid[(size_t)n*Fout + o];
            out[(size_t)n*Fout + o] = v;
        }
    }
}

// ---------------- BN batch statistics (deterministic, 8 blocks) ----------------
__global__ void bn_stats_kernel(const float* __restrict__ X) {
    int tx = threadIdx.x & 31, ty = threadIdx.x >> 5;  // 8 row-groups
    int c = blockIdx.x*32 + tx;
    float s = 0.f, sq = 0.f;
    for (int n = ty; n < NN; n += 8) {
        float v = X[(size_t)n*HDIM + c];
        s += v; sq += v*v;
    }
    __shared__ float sh1[8][32], sh2[8][32];
    sh1[ty][tx] = s; sh2[ty][tx] = sq;
    __syncthreads();
    if (ty == 0) {
        #pragma unroll
        for (int k = 1; k < 8; k++) { s += sh1[k][tx]; sq += sh2[k][tx]; }
        float mu = s / (float)NN;
        g_mu[c]  = mu;
        g_var[c] = sq / (float)NN - mu*mu;
    }
}

// ---------------- fused BN apply + LayerNorm + ELU (one block per row) ----------------
__global__ void bn_ln_elu_kernel(const float* __restrict__ pre,
                                 const float* __restrict__ bg, const float* __restrict__ bb,
                                 const float* __restrict__ lg, const float* __restrict__ lb,
                                 float* __restrict__ out)
{
    int n = blockIdx.x, c = threadIdx.x;   // 256 threads
    float x = pre[(size_t)n*HDIM + c];
    x = (x - g_mu[c]) * rsqrtf(g_var[c] + 1e-5f) * bg[c] + bb[c];
    __shared__ float s1[HDIM], s2[HDIM];
    s1[c] = x; s2[c] = x*x;
    __syncthreads();
    for (int st = HDIM/2; st > 0; st >>= 1) {
        if (c < st) { s1[c] += s1[c+st]; s2[c] += s2[c+st]; }
        __syncthreads();
    }
    float m = s1[0] / (float)HDIM;
    float v = s2[0] / (float)HDIM - m*m;
    x = (x - m) * rsqrtf(v + 1e-5f) * lg[c] + lb[c];
    out[(size_t)n*HDIM + c] = (x > 0.f) ? x : expm1f(x);
}

// ---------------- launch ----------------
extern "C" void kernel_launch(void* const* d_in, const int* in_sizes, int n_in,
                              void* d_out, int out_size) {
    const float* X    = (const float*)d_in[0];
    const float* H    = (const float*)d_in[1];
    const float* W1   = (const float*)d_in[2];
    const float* W2   = (const float*)d_in[3];
    const float* W3   = (const float*)d_in[4];
    const float* imp  = (const float*)d_in[5];
    const float* b1   = (const float*)d_in[6];
    const float* b2   = (const float*)d_in[7];
    const float* b3   = (const float*)d_in[8];
    const float* bng  = (const float*)d_in[9];
    const float* bnb  = (const float*)d_in[10];
    const float* lng  = (const float*)d_in[11];
    const float* lnb  = (const float*)d_in[12];
    const float* rel  = (const float*)d_in[13];
    float* out = (float*)d_out;

    float *pT, *pHn, *pPre, *pH, *pDv, *pCE, *pSig;
    unsigned *pMN, *pME;
    cudaGetSymbolAddress((void**)&pT,  g_T);
    cudaGetSymbolAddress((void**)&pHn, g_Hn);
    cudaGetSymbolAddress((void**)&pPre,g_pre);
    cudaGetSymbolAddress((void**)&pH,  g_h);
    cudaGetSymbolAddress((void**)&pDv, g_dv);
    cudaGetSymbolAddress((void**)&pCE, g_cE);
    cudaGetSymbolAddress((void**)&pSig,g_sig);
    cudaGetSymbolAddress((void**)&pMN, g_maskN);
    cudaGetSymbolAddress((void**)&pME, g_maskE);

    // ---- structure precompute (shared by all 3 conv layers) ----
    prep_kernel<<<1, 32>>>(rel, imp);
    build_maskN_kernel<<<RR*NN/8, 256>>>(H);
    transpose_mask_kernel<<<RR*(NN/32)*(EE/32)/8, 256>>>();
    build_cE_kernel<<<RR*EE/8, 256>>>();

    // ---- layer 1 (Fin = FF = 128) ----
    gather_kernel<<<dim3(RR*EE/64, 1), 256>>>(pME, EE, NN, X, 0, FF, pDv, pCE, pT, HDIM);
    gather_kernel<<<dim3(RR*NN/64, 1), 256>>>(pMN, NN, EE, pT, (long long)EE*HDIM, HDIM,
                                              nullptr, pDv, pHn, HDIM);
    gemm_kernel<<<dim3(NN/64, HDIM/64), 256>>>(pHn, FF, HDIM, W1, pSig + 0*RR, b1, nullptr, pPre);
    bn_stats_kernel<<<HDIM/32, 256>>>(pPre);
    bn_ln_elu_kernel<<<NN, HDIM>>>(pPre, bng, bnb, lng, lnb, pH);

    // ---- layer 2 (Fin = HDIM = 256) ----
    gather_kernel<<<dim3(RR*EE/64, 2), 256>>>(pME, EE, NN, pH, 0, HDIM, pDv, pCE, pT, HDIM);
    gather_kernel<<<dim3(RR*NN/64, 2), 256>>>(pMN, NN, EE, pT, (long long)EE*HDIM, HDIM,
                                              nullptr, pDv, pHn, HDIM);
    gemm_kernel<<<dim3(NN/64, HDIM/64), 256>>>(pHn, HDIM, HDIM, W2, pSig + 1*RR, b2, nullptr, pPre);
    bn_stats_kernel<<<HDIM/32, 256>>>(pPre);
    bn_ln_elu_kernel<<<NN, HDIM>>>(pPre, bng + HDIM, bnb + HDIM, lng + HDIM, lnb + HDIM, pH);

    // ---- layer 3 (Fin = HDIM, Fout = FF) + residual ----
    gather_kernel<<<dim3(RR*EE/64, 2), 256>>>(pME, EE, NN, pH, 0, HDIM, pDv, pCE, pT, HDIM);
    gather_kernel<<<dim3(RR*NN/64, 2), 256>>>(pMN, NN, EE, pT, (long long)EE*HDIM, HDIM,
                                              nullptr, pDv, pHn, HDIM);
    gemm_kernel<<<dim3(NN/64, FF/64), 256>>>(pHn, HDIM, FF, W3, pSig + 2*RR, b3, X, out);
}

// round 2
// speedup vs baseline: 2.4317x; 2.4317x over previous
#include <cuda_runtime.h>
#include <cuda_pipeline.h>
#include <math.h>

#define RR 4
#define NN 4096
#define EE 2048
#define FF 128
#define HDIM 256
#define EW (EE/32)   // 64 mask words per node row
#define NW (NN/32)   // 128 mask words per edge row
#define PART_S4 (RR*NN*64)   // float4 stride between partial buffers

// ---------------- device scratch (allocation-free: static globals) ----------------
__device__ float    g_rw[RR];
__device__ float    g_sig[3][RR];
__device__ float    g_dv[RR*NN];
__device__ float    g_cE[RR*EE];
__device__ unsigned g_maskN[(size_t)RR*NN*EW];
__device__ unsigned g_maskE[(size_t)RR*EE*NW];
__device__ float4   g_Xs [(size_t)RR*NN*64];   // dv-scaled per-relation source (stride 64 f4)
__device__ float4   g_T  [(size_t)RR*EE*64];   // edge features
__device__ float4   g_Hn [(size_t)RR*NN*64];   // per-relation node features
__device__ float4   g_pre[(size_t)NN*64];
__device__ float4   g_h  [(size_t)NN*64];
__device__ float4   g_part[(size_t)4*PART_S4]; // split-source partials (4 x 16MB)
__device__ float    g_mu[HDIM], g_var[HDIM];

// ---------------- prep ----------------
__global__ void prep_kernel(const float* __restrict__ rel, const float* __restrict__ imp) {
    if (threadIdx.x == 0) {
        float m = -1e30f;
        for (int r = 0; r < RR; r++) m = fmaxf(m, rel[r]);
        float e[RR], s = 0.f;
        for (int r = 0; r < RR; r++) { e[r] = expf(rel[r] - m); s += e[r]; }
        for (int r = 0; r < RR; r++) g_rw[r] = e[r] / s;
        for (int l = 0; l < 3; l++)
            for (int r = 0; r < RR; r++)
                g_sig[l][r] = 1.f / (1.f + expf(-imp[l*RR + r]));
    }
}

// ---------------- bitmask build: one warp per (r,n) row ----------------
__global__ void build_maskN_kernel(const float* __restrict__ H) {
    int gw   = blockIdx.x * (blockDim.x >> 5) + (threadIdx.x >> 5);
    int lane = threadIdx.x & 31;
    if (gw >= RR*NN) return;
    int r = gw / NN;
    const float* row = H + (size_t)gw * EE;
    unsigned w0 = 0, w1 = 0;
    int cnt = 0;
    #pragma unroll 8
    for (int k = 0; k < 64; k++) {
        float v = row[k*32 + lane];
        unsigned b = __ballot_sync(0xffffffffu, v != 0.0f);
        cnt += (v != 0.0f) ? 1 : 0;
        if (k == lane)      w0 = b;
        if (k == lane + 32) w1 = b;
    }
    g_maskN[(size_t)gw*EW + lane]      = w0;
    g_maskN[(size_t)gw*EW + 32 + lane] = w1;
    int tot = __reduce_add_sync(0xffffffffu, cnt);
    if (lane == 0)
        g_dv[gw] = 1.0f / sqrtf(g_rw[r] * (float)tot + 1e-8f);
}

// ---------------- 32x32 bit transpose ----------------
__global__ void transpose_mask_kernel() {
    const int tilesPerR = (NN/32)*(EE/32);
    int gw   = blockIdx.x * (blockDim.x >> 5) + (threadIdx.x >> 5);
    int lane = threadIdx.x & 31;
    if (gw >= RR * tilesPerR) return;
    int r   = gw / tilesPerR;
    int rem = gw % tilesPerR;
    int nb  = rem / (EE/32);
    int eb  = rem % (EE/32);
    unsigned w = g_maskN[((size_t)r*NN + nb*32 + lane)*EW + eb];
    unsigned out = 0;
    #pragma unroll
    for (int j = 0; j < 32; j++) {
        unsigned b = __ballot_sync(0xffffffffu, (w >> j) & 1u);
        if (lane == j) out = b;
    }
    g_maskE[((size_t)r*EE + eb*32 + lane)*NW + nb] = out;
}

// ---------------- edge constants ----------------
__global__ void build_cE_kernel() {
    int gw   = blockIdx.x * (blockDim.x >> 5) + (threadIdx.x >> 5);
    int lane = threadIdx.x & 31;
    if (gw >= RR*EE) return;
    int r = gw / EE;
    const unsigned* row = g_maskE + (size_t)gw * NW;
    int cnt = 0;
    for (int k = lane; k < NW; k += 32) cnt += __popc(row[k]);
    cnt = __reduce_add_sync(0xffffffffu, cnt);
    if (lane == 0) {
        float rw = g_rw[r];
        g_cE[gw] = rw * rw / (rw * (float)cnt + 1e-8f);
    }
}

// ---------------- pre-scale source by dv: dst[r][n][c] = dv[r,n]*src[n][c] ----------------
__global__ void prescale_kernel(const float4* __restrict__ src, int srcStride4, int cshift,
                                float4* __restrict__ dst) {
    int idx = blockIdx.x*256 + threadIdx.x;   // over R*NN*cols4
    int c  = idx & ((1<<cshift)-1);
    int rn = idx >> cshift;
    int n  = rn & (NN-1);
    float  s = g_dv[rn];
    float4 v = src[(size_t)n*srcStride4 + c];
    dst[((size_t)rn<<6) + c] = make_float4(s*v.x, s*v.y, s*v.z, s*v.w);
}

// ---------------- pipelined masked gather-SpMM ----------------
// acc[t][c] = sum_{s: bit set} src[r][s][c];  3-stage cp.async pipeline, 32-src-row chunks.
// grid: x = R*(Tn/64), y = colblocks (128 cols each), z = P (source split).
// outScale!=null (requires P==1): write outScale[r,t]*acc to out; else write raw partial to g_part[p].
__global__ void __launch_bounds__(256) gather_kernel(
    const unsigned* __restrict__ mask, int Tn, int Sw,
    const float4* __restrict__ src, int relStride4, int srcRowStride4,
    int chunksPerP,
    const float* __restrict__ outScale,
    float4* __restrict__ out)
{
    __shared__ float4 sbuf[3*1024];   // 3 stages x 32 rows x 32 float4 = 48KB

    const int tid  = threadIdx.x, lane = tid & 31, w = tid >> 5;
    const int tilesT = Tn >> 6;
    const int r  = blockIdx.x / tilesT;
    const int t0 = (blockIdx.x % tilesT) << 6;
    const int p  = blockIdx.z;
    const int colIdx4 = (blockIdx.y << 5) + lane;
    const float4* srcB = src + (size_t)r*relStride4 + (blockIdx.y << 5);
    const int wordBase = p * chunksPerP;
    const int rowBase  = wordBase << 5;
    const unsigned* mbase = mask + ((size_t)(r*Tn + t0 + (w<<3)))*Sw + wordBase;

    auto stage = [&](int c) {
        int st = c % 3;
        int gbase = rowBase + (c << 5);
        #pragma unroll
        for (int k = 0; k < 4; k++) {
            int i = tid + (k << 8);
            int row = i >> 5, col = i & 31;
            __pipeline_memcpy_async(&sbuf[(st<<10) + (row<<5) + col],
                                    srcB + (size_t)(gbase+row)*srcRowStride4 + col, 16);
        }
        __pipeline_commit();
    };

    float4 acc[8];
    #pragma unroll
    for (int j = 0; j < 8; j++) acc[j] = make_float4(0.f,0.f,0.f,0.f);

    stage(0);
    stage(1);
    for (int c = 0; c < chunksPerP; c++) {
        __syncthreads();                 // slot (c+2)%3 free (compute(c-1) done everywhere)
        if (c + 2 < chunksPerP) stage(c+2);
        else                    __pipeline_commit();   // keep group accounting uniform
        __pipeline_wait_prior(2);        // chunk c's copies complete (this thread)
        __syncthreads();                 // chunk c complete block-wide
        const float4* bufc = sbuf + ((c % 3) << 10);
        #pragma unroll
        for (int j = 0; j < 8; j++) {
            unsigned b = mbase[(size_t)j*Sw + c];
            while (b) {
                int s = __ffs(b) - 1; b &= b - 1;
                float4 v = bufc[(s << 5) + lane];
                acc[j].x += v.x; acc[j].y += v.y; acc[j].z += v.z; acc[j].w += v.w;
            }
        }
    }

    float4* dst = outScale ? out : (g_part + (size_t)p * PART_S4);
    #pragma unroll
    for (int j = 0; j < 8; j++) {
        int t = t0 + (w<<3) + j;
        size_t o = ((size_t)(r*Tn + t) << 6) + colIdx4;
        float4 v = acc[j];
        if (outScale) {
            float sc = outScale[r*Tn + t];
            v.x *= sc; v.y *= sc; v.z *= sc; v.w *= sc;
        }
        dst[o] = v;
    }
}

// ---------------- combine split-source partials: out = scale * sum_p part[p] ----------------
__global__ void combine_kernel(int P, int nRows, int cshift,
                               const float* __restrict__ scale, float4* __restrict__ out) {
    int idx = blockIdx.x*256 + threadIdx.x;
    int row = idx >> cshift;
    if (row >= nRows) return;
    int c = idx & ((1<<cshift)-1);
    size_t o = ((size_t)row << 6) + c;
    float4 s = g_part[o];
    for (int p = 1; p < P; p++) {
        float4 v = g_part[(size_t)p*PART_S4 + o];
        s.x += v.x; s.y += v.y; s.z += v.z; s.w += v.w;
    }
    float sc = scale[row];
    out[o] = make_float4(sc*s.x, sc*s.y, sc*s.z, sc*s.w);
}

// ---------------- relation-summed projection GEMM + epilogue ----------------
__global__ void gemm_kernel(const float* __restrict__ A, int Fin, int Fout,
                            const float* __restrict__ W,
                            const float* __restrict__ sig,
                            const float* __restrict__ bias,
                            const float* __restrict__ resid,
                            float* __restrict__ out)
{
    __shared__ float sA[16][68];
    __shared__ float sB[16][68];
    const int n0 = blockIdx.x << 6, o0 = blockIdx.y << 6;
    const int tid = threadIdx.x;
    const int tx = tid & 15, ty = tid >> 4;

    float acc[4][4];
    #pragma unroll
    for (int i = 0; i < 4; i++)
        #pragma unroll
        for (int j = 0; j < 4; j++) acc[i][j] = 0.f;

    for (int r = 0; r < RR; r++) {
        const float sr = sig[r];
        const float* Ar = A + (size_t)r * NN * HDIM;
        const float* Wr = W + (size_t)r * Fin * Fout;
        for (int f0 = 0; f0 < Fin; f0 += 16) {
            {
                int k = tid & 15, mg = tid >> 4;
                #pragma unroll
                for (int mm = 0; mm < 4; mm++) {
                    int m = mg*4 + mm;
                    sA[k][m] = Ar[(size_t)(n0+m)*HDIM + f0 + k];
                }
            }
            {
                int j = tid & 63, k0 = tid >> 6;
                #pragma unroll
                for (int kk = 0; kk < 4; kk++) {
                    int k = k0 + kk*4;
                    sB[k][j] = sr * Wr[(size_t)(f0+k)*Fout + o0 + j];
                }
            }
            __syncthreads();
            #pragma unroll
            for (int k = 0; k < 16; k++) {
                float4 a = *reinterpret_cast<const float4*>(&sA[k][ty*4]);
                float4 b = *reinterpret_cast<const float4*>(&sB[k][tx*4]);
                float av[4] = {a.x, a.y, a.z, a.w};
                float bv[4] = {b.x, b.y, b.z, b.w};
                #pragma unroll
                for (int i = 0; i < 4; i++)
                    #pragma unroll
                    for (int j = 0; j < 4; j++)
                        acc[i][j] += av[i] * bv[j];
            }
            __syncthreads();
        }
    }

    #pragma unroll
    for (int i = 0; i < 4; i++) {
        int n = n0 + ty*4 + i;
        #pragma unroll
        for (int j = 0; j < 4; j++) {
            int o = o0 + tx*4 + j;
            float v = acc[i][j] + bias[o];
            if (resid) v += resid[(size_t)n*Fout + o];
            out[(size_t)n*Fout + o] = v;
        }
    }
}

// ---------------- BN batch statistics ----------------
__global__ void bn_stats_kernel(const float* __restrict__ X) {
    int tx = threadIdx.x & 31, ty = threadIdx.x >> 5;
    int c = blockIdx.x*32 + tx;
    float s = 0.f, sq = 0.f;
    for (int n = ty; n < NN; n += 8) {
        float v = X[(size_t)n*HDIM + c];
        s += v; sq += v*v;
    }
    __shared__ float sh1[8][32], sh2[8][32];
    sh1[ty][tx] = s; sh2[ty][tx] = sq;
    __syncthreads();
    if (ty == 0) {
        #pragma unroll
        for (int k = 1; k < 8; k++) { s += sh1[k][tx]; sq += sh2[k][tx]; }
        float mu = s / (float)NN;
        g_mu[c]  = mu;
        g_var[c] = sq / (float)NN - mu*mu;
    }
}

// ---------------- fused BN apply + LayerNorm + ELU ----------------
__global__ void bn_ln_elu_kernel(const float* __restrict__ pre,
                                 const float* __restrict__ bg, const float* __restrict__ bb,
                                 const float* __restrict__ lg, const float* __restrict__ lb,
                                 float* __restrict__ out)
{
    int n = blockIdx.x, c = threadIdx.x;
    float x = pre[(size_t)n*HDIM + c];
    x = (x - g_mu[c]) * rsqrtf(g_var[c] + 1e-5f) * bg[c] + bb[c];
    float s1 = x, s2 = x*x;
    #pragma unroll
    for (int o = 16; o > 0; o >>= 1) {
        s1 += __shfl_xor_sync(0xffffffffu, s1, o);
        s2 += __shfl_xor_sync(0xffffffffu, s2, o);
    }
    __shared__ float a1[8], a2[8];
    if ((c & 31) == 0) { a1[c>>5] = s1; a2[c>>5] = s2; }
    __syncthreads();
    s1 = 0.f; s2 = 0.f;
    #pragma unroll
    for (int k = 0; k < 8; k++) { s1 += a1[k]; s2 += a2[k]; }
    float m = s1 * (1.f/256.f);
    float v = s2 * (1.f/256.f) - m*m;
    x = (x - m) * rsqrtf(v + 1e-5f) * lg[c] + lb[c];
    out[(size_t)n*HDIM + c] = (x > 0.f) ? x : expm1f(x);
}

// ---------------- launch ----------------
extern "C" void kernel_launch(void* const* d_in, const int* in_sizes, int n_in,
                              void* d_out, int out_size) {
    const float* X    = (const float*)d_in[0];
    const float* H    = (const float*)d_in[1];
    const float* W1   = (const float*)d_in[2];
    const float* W2   = (const float*)d_in[3];
    const float* W3   = (const float*)d_in[4];
    const float* imp  = (const float*)d_in[5];
    const float* b1   = (const float*)d_in[6];
    const float* b2   = (const float*)d_in[7];
    const float* b3   = (const float*)d_in[8];
    const float* bng  = (const float*)d_in[9];
    const float* bnb  = (const float*)d_in[10];
    const float* lng  = (const float*)d_in[11];
    const float* lnb  = (const float*)d_in[12];
    const float* rel  = (const float*)d_in[13];
    float* out = (float*)d_out;

    float *pDv, *pCE, *pSig, *pMu;
    float4 *pXs, *pT, *pHn, *pPre, *pH;
    unsigned *pMN, *pME;
    cudaGetSymbolAddress((void**)&pDv, g_dv);
    cudaGetSymbolAddress((void**)&pCE, g_cE);
    cudaGetSymbolAddress((void**)&pSig,g_sig);
    cudaGetSymbolAddress((void**)&pMu, g_mu);
    cudaGetSymbolAddress((void**)&pXs, g_Xs);
    cudaGetSymbolAddress((void**)&pT,  g_T);
    cudaGetSymbolAddress((void**)&pHn, g_Hn);
    cudaGetSymbolAddress((void**)&pPre,g_pre);
    cudaGetSymbolAddress((void**)&pH,  g_h);
    cudaGetSymbolAddress((void**)&pMN, g_maskN);
    cudaGetSymbolAddress((void**)&pME, g_maskE);

    // ---- structure precompute (shared by all 3 conv layers) ----
    prep_kernel<<<1, 32>>>(rel, imp);
    build_maskN_kernel<<<RR*NN/8, 256>>>(H);
    transpose_mask_kernel<<<RR*(NN/32)*(EE/32)/8, 256>>>();
    build_cE_kernel<<<RR*EE/8, 256>>>();

    const int tilesE = EE/64, tilesN = NN/64;

    // ---- layer 1 (cols = 128 -> colb 1, cshift 5) ----
    prescale_kernel<<<RR*NN*32/256, 256>>>((const float4*)X, 32, 5, pXs);
    gather_kernel<<<dim3(RR*tilesE, 1, 4), 256>>>(pME, EE, NW, pXs, NN*64, 64, (NN/32)/4, nullptr, nullptr);
    combine_kernel<<<RR*EE*32/256, 256>>>(4, RR*EE, 5, pCE, pT);
    gather_kernel<<<dim3(RR*tilesN, 1, 2), 256>>>(pMN, NN, EW, pT, EE*64, 64, (EE/32)/2, nullptr, nullptr);
    combine_kernel<<<RR*NN*32/256, 256>>>(2, RR*NN, 5, pDv, pHn);
    gemm_kernel<<<dim3(NN/64, HDIM/64), 256>>>((const float*)pHn, FF, HDIM, W1, pSig + 0*RR, b1, nullptr, (float*)pPre);
    bn_stats_kernel<<<HDIM/32, 256>>>((const float*)pPre);
    bn_ln_elu_kernel<<<NN, HDIM>>>((const float*)pPre, bng, bnb, lng, lnb, (float*)pH);

    // ---- layer 2 (cols = 256 -> colb 2, cshift 6) ----
    prescale_kernel<<<RR*NN*64/256, 256>>>(pH, 64, 6, pXs);
    gather_kernel<<<dim3(RR*tilesE, 2, 2), 256>>>(pME, EE, NW, pXs, NN*64, 64, (NN/32)/2, nullptr, nullptr);
    combine_kernel<<<RR*EE*64/256, 256>>>(2, RR*EE, 6, pCE, pT);
    gather_kernel<<<dim3(RR*tilesN, 2, 1), 256>>>(pMN, NN, EW, pT, EE*64, 64, (EE/32), pDv, pHn);
    gemm_kernel<<<dim3(NN/64, HDIM/64), 256>>>((const float*)pHn, HDIM, HDIM, W2, pSig + 1*RR, b2, nullptr, (float*)pPre);
    bn_stats_kernel<<<HDIM/32, 256>>>((const float*)pPre);
    bn_ln_elu_kernel<<<NN, HDIM>>>((const float*)pPre, bng + HDIM, bnb + HDIM, lng + HDIM, lnb + HDIM, (float*)pH);

    // ---- layer 3 (cols = 256) + residual ----
    prescale_kernel<<<RR*NN*64/256, 256>>>(pH, 64, 6, pXs);
    gather_kernel<<<dim3(RR*tilesE, 2, 2), 256>>>(pME, EE, NW, pXs, NN*64, 64, (NN/32)/2, nullptr, nullptr);
    combine_kernel<<<RR*EE*64/256, 256>>>(2, RR*EE, 6, pCE, pT);
    gather_kernel<<<dim3(RR*tilesN, 2, 1), 256>>>(pMN, NN, EW, pT, EE*64, 64, (EE/32), pDv, pHn);
    gemm_kernel<<<dim3(NN/64, FF/64), 256>>>((const float*)pHn, HDIM, FF, W3, pSig + 2*RR, b3, X, out);
}